// round 8
// baseline (speedup 1.0000x reference)
#include <cuda_runtime.h>
#include <cuda_bf16.h>
#include <cuda_fp16.h>
#include <cstdint>
#include <math.h>

// Problem constants
#define B_   4
#define SEQ  2048
#define EMB  1024
#define NH   16
#define HD   64
#define SZ   (B_*SEQ*EMB)     // 8,388,608
#define LOCALK 128
#define SCALE  0.125f
#define NEGF  (-1e30f)

// Scratch
__device__ __align__(16) __half g_xhi[SZ], g_xlo[SZ];            // x split (fp16)
__device__ __align__(16) __half g_ahi[SZ], g_alo[SZ];            // attn out split (fp16)
__device__ __align__(16) __half g_wh[4][EMB*EMB];                // weights (fp16)
__device__ __align__(16) __nv_bfloat16 g_qhi[SZ], g_qlo[SZ];     // [bh][t][d], pre-scaled
__device__ __align__(16) __nv_bfloat16 g_khi[SZ], g_klo[SZ];     // [bh][t][d]
__device__ __align__(16) __nv_bfloat16 g_vthi[SZ], g_vtlo[SZ];   // [bh][d][t]

// ============================================================================
// Helpers
// ============================================================================
__device__ __forceinline__ uint32_t smem_u32(const void* p) {
    uint32_t a;
    asm("{ .reg .u64 t; cvta.to.shared.u64 t, %1; cvt.u32.u64 %0, t; }" : "=r"(a) : "l"(p));
    return a;
}
#define CP16(dst, src) asm volatile("cp.async.cg.shared.global [%0], [%1], 16;" :: "r"(dst), "l"(src))
#define CP_COMMIT()    asm volatile("cp.async.commit_group;" ::: "memory")
#define CP_WAIT1()     asm volatile("cp.async.wait_group 1;" ::: "memory")
#define CP_WAIT0()     asm volatile("cp.async.wait_group 0;" ::: "memory")

__device__ __forceinline__ void ldsm4(uint32_t addr, uint32_t* r) {
    asm volatile("ldmatrix.sync.aligned.m8n8.x4.shared.b16 {%0,%1,%2,%3}, [%4];"
                 : "=r"(r[0]), "=r"(r[1]), "=r"(r[2]), "=r"(r[3]) : "r"(addr));
}
__device__ __forceinline__ void mma_bf16(float* c, uint32_t a0, uint32_t a1, uint32_t a2,
                                         uint32_t a3, uint32_t b0, uint32_t b1) {
    asm volatile(
        "mma.sync.aligned.m16n8k16.row.col.f32.bf16.bf16.f32 "
        "{%0,%1,%2,%3}, {%4,%5,%6,%7}, {%8,%9}, {%0,%1,%2,%3};"
        : "+f"(c[0]), "+f"(c[1]), "+f"(c[2]), "+f"(c[3])
        : "r"(a0), "r"(a1), "r"(a2), "r"(a3), "r"(b0), "r"(b1));
}
__device__ __forceinline__ void mma_f16(float* c, uint32_t a0, uint32_t a1, uint32_t a2,
                                        uint32_t a3, uint32_t b0, uint32_t b1) {
    asm volatile(
        "mma.sync.aligned.m16n8k16.row.col.f32.f16.f16.f32 "
        "{%0,%1,%2,%3}, {%4,%5,%6,%7}, {%8,%9}, {%0,%1,%2,%3};"
        : "+f"(c[0]), "+f"(c[1]), "+f"(c[2]), "+f"(c[3])
        : "r"(a0), "r"(a1), "r"(a2), "r"(a3), "r"(b0), "r"(b1));
}
// bf16 packing (attention P-split): {lo16 = a.hi16, hi16 = b.hi16}
__device__ __forceinline__ uint32_t prmt_hi(float a, float b) {
    uint32_t d;
    asm("prmt.b32 %0, %1, %2, 0x7632;" : "=r"(d) : "r"(__float_as_uint(a)), "r"(__float_as_uint(b)));
    return d;
}
__device__ __forceinline__ uint32_t packbf(float lo, float hi) {
    uint32_t d;
    asm("cvt.rn.bf16x2.f32 %0, %1, %2;" : "=r"(d) : "f"(hi), "f"(lo));
    return d;
}
__device__ __forceinline__ float truncbf(float v) {
    return __uint_as_float(__float_as_uint(v) & 0xFFFF0000u);
}

// ============================================================================
// Conversions.  dsel 0: x -> fp16 hi/lo split.  dsel 1..4: W -> fp16.
// ============================================================================
__global__ __launch_bounds__(256) void split_kernel(const float* __restrict__ src,
                                                    int dsel, int n4) {
    int i = blockIdx.x * 256 + threadIdx.x;
    if (i >= n4) return;
    float4 v = ((const float4*)src)[i];
    __half h0 = __float2half_rn(v.x), h1 = __float2half_rn(v.y);
    __half h2 = __float2half_rn(v.z), h3 = __float2half_rn(v.w);
    if (dsel == 0) {
        __half l0 = __float2half_rn(v.x - __half2float(h0));
        __half l1 = __float2half_rn(v.y - __half2float(h1));
        __half l2 = __float2half_rn(v.z - __half2float(h2));
        __half l3 = __float2half_rn(v.w - __half2float(h3));
        __half2* H = (__half2*)g_xhi;  __half2* L = (__half2*)g_xlo;
        H[2*i]   = __halves2half2(h0, h1);  H[2*i+1] = __halves2half2(h2, h3);
        L[2*i]   = __halves2half2(l0, l1);  L[2*i+1] = __halves2half2(l2, l3);
    } else {
        __half2* H = (__half2*)g_wh[dsel-1];
        H[2*i]   = __halves2half2(h0, h1);  H[2*i+1] = __halves2half2(h2, h3);
    }
}

// ============================================================================
// 2-pass split-fp16 GEMM: C = (Ahi+Alo) @ W~^T + bias
// 128x128 tile, BK=32, 3 smem tiles/stage (Ahi, Alo, W), 3-stage pipeline.
// fused=1: QKV in one launch, w_idx = blockIdx.x>>3, scatter to split-bf16 QKV.
// fused=0: O projection, fp32 out.
// ============================================================================
#define RS    40
#define GTB   (128*RS*2)          // 10240 bytes per tile
#define GSTG  (3*GTB)             // 30720 per stage
#define GSMEM (3*GSTG)            // 92160
#define GNIT  32

__global__ __launch_bounds__(256) void gemm_hmma(
    const float* __restrict__ b0, const float* __restrict__ b1,
    const float* __restrict__ b2, float* __restrict__ out_ext,
    int a_sel, int fused)
{
    extern __shared__ char smc[];
    uint32_t smbase = smem_u32(smc);
    int tid = threadIdx.x, lane = tid & 31, wid = tid >> 5;
    int mb = blockIdx.y * 128;
    int w_idx, nb, dst_sel;
    const float* bias;
    if (fused) {
        w_idx = blockIdx.x >> 3;  nb = (blockIdx.x & 7) * 128;  dst_sel = w_idx;
        bias = (w_idx == 0) ? b0 : (w_idx == 1) ? b1 : b2;
    } else {
        w_idx = 3;  nb = blockIdx.x * 128;  dst_sel = 3;  bias = b0;
    }
    int wm = (wid >> 2) * 64, wn = (wid & 3) * 32;

    const __half* Ahi = a_sel ? g_ahi : g_xhi;
    const __half* Alo = a_sel ? g_alo : g_xlo;
    const __half* Bw  = g_wh[w_idx];

    int r0c = tid >> 2;                  // 0..63
    int r1c = r0c + 64;                  // 64..127
    int cc0 = (tid & 3) * 8;

    float acc[4][4][4];
    #pragma unroll
    for (int i = 0; i < 4; i++)
        #pragma unroll
        for (int j = 0; j < 4; j++)
            #pragma unroll
            for (int r = 0; r < 4; r++) acc[i][j][r] = 0.f;

    auto stage = [&](int kidx) {
        int kk = kidx * 32;
        uint32_t buf = smbase + (kidx % 3) * GSTG;
        const __half* p0 = Ahi + (size_t)mb * EMB + kk;
        const __half* p1 = Alo + (size_t)mb * EMB + kk;
        const __half* p2 = Bw  + (size_t)nb * EMB + kk;
        CP16(buf + 0*GTB + (r0c*RS + cc0)*2, p0 + (size_t)r0c*EMB + cc0);
        CP16(buf + 0*GTB + (r1c*RS + cc0)*2, p0 + (size_t)r1c*EMB + cc0);
        CP16(buf + 1*GTB + (r0c*RS + cc0)*2, p1 + (size_t)r0c*EMB + cc0);
        CP16(buf + 1*GTB + (r1c*RS + cc0)*2, p1 + (size_t)r1c*EMB + cc0);
        CP16(buf + 2*GTB + (r0c*RS + cc0)*2, p2 + (size_t)r0c*EMB + cc0);
        CP16(buf + 2*GTB + (r1c*RS + cc0)*2, p2 + (size_t)r1c*EMB + cc0);
        CP_COMMIT();
    };

    stage(0); stage(1);

    int a_row = wm + (lane & 15);
    int a_half = (lane & 16) ? 8 : 0;
    int b_row = wn + (lane & 7) + ((lane & 16) ? 8 : 0);
    int b_half = (lane & 8) ? 8 : 0;

    for (int i = 0; i < GNIT; i++) {
        if (i == GNIT-1) CP_WAIT0(); else CP_WAIT1();
        __syncthreads();
        if (i + 2 < GNIT) stage(i + 2);

        uint32_t buf = smbase + (i % 3) * GSTG;
        #pragma unroll
        for (int ks = 0; ks < 2; ks++) {
            uint32_t ah[4][4], al[4][4], bh[2][4];
            #pragma unroll
            for (int mi = 0; mi < 4; mi++) {
                uint32_t off = ((a_row + mi*16)*RS + ks*16 + a_half)*2;
                ldsm4(buf + 0*GTB + off, ah[mi]);
                ldsm4(buf + 1*GTB + off, al[mi]);
            }
            #pragma unroll
            for (int np = 0; np < 2; np++) {
                uint32_t off = ((b_row + np*16)*RS + ks*16 + b_half)*2;
                ldsm4(buf + 2*GTB + off, bh[np]);
            }
            #pragma unroll
            for (int mi = 0; mi < 4; mi++)
                #pragma unroll
                for (int nj = 0; nj < 4; nj++) {
                    uint32_t q0 = bh[nj>>1][(nj&1)*2], q1 = bh[nj>>1][(nj&1)*2+1];
                    mma_f16(acc[mi][nj], ah[mi][0], ah[mi][1], ah[mi][2], ah[mi][3], q0, q1);
                    mma_f16(acc[mi][nj], al[mi][0], al[mi][1], al[mi][2], al[mi][3], q0, q1);
                }
        }
    }

    // Epilogue
    #pragma unroll
    for (int mi = 0; mi < 4; mi++) {
        #pragma unroll
        for (int nj = 0; nj < 4; nj++) {
            int row = mb + wm + mi*16 + (lane >> 2);
            int col = nb + wn + nj*8 + 2*(lane & 3);
            float2 bv = *(const float2*)(bias + col);
            #pragma unroll
            for (int half = 0; half < 2; half++) {
                int rr = row + half*8;
                float v0 = acc[mi][nj][2*half+0] + bv.x;
                float v1 = acc[mi][nj][2*half+1] + bv.y;
                if (dst_sel == 3) {
                    *(float2*)(out_ext + (size_t)rr * EMB + col) = make_float2(v0, v1);
                    continue;
                }
                int bb = rr >> 11, tt = rr & 2047;
                int hh = col >> 6, d0 = col & 63;
                if (dst_sel == 0) { v0 *= SCALE; v1 *= SCALE; }
                __nv_bfloat16 h0 = __float2bfloat16(v0), h1 = __float2bfloat16(v1);
                __nv_bfloat16 l0 = __float2bfloat16(v0 - __bfloat162float(h0));
                __nv_bfloat16 l1 = __float2bfloat16(v1 - __bfloat162float(h1));
                if (dst_sel == 2) {
                    size_t base = ((size_t)(bb*NH + hh) * HD + d0) * SEQ + tt;
                    g_vthi[base] = h0;  g_vthi[base + SEQ] = h1;
                    g_vtlo[base] = l0;  g_vtlo[base + SEQ] = l1;
                } else {
                    size_t base = ((size_t)(bb*NH + hh) * SEQ + tt) * HD + d0;
                    __nv_bfloat16* Hd = dst_sel ? g_khi : g_qhi;
                    __nv_bfloat16* Ld = dst_sel ? g_klo : g_qlo;
                    *(__nv_bfloat162*)(Hd + base) = __nv_bfloat162(h0, h1);
                    *(__nv_bfloat162*)(Ld + base) = __nv_bfloat162(l0, l1);
                }
            }
        }
    }
}

// ============================================================================
// Tensor-core attention (round-5, known-good), epilogue now writes fp16 split.
// ============================================================================
#define QT   64
#define KT   64
#define RSA  72
#define AQB  (64*RSA*2)
#define ASTG (4*AQB)
#define ASMEM (2*AQB + 2*ASTG)

__global__ __launch_bounds__(128) void attn_tc()
{
    extern __shared__ char smc[];
    uint32_t sb = smem_u32(smc);
    int tid = threadIdx.x, lane = tid & 31, wid = tid >> 5;
    int bh = blockIdx.y, h = bh & (NH-1), bb = bh >> 4;
    int q0 = blockIdx.x * QT;

    const __nv_bfloat16* Qhp = g_qhi + ((size_t)bh*SEQ + q0) * HD;
    const __nv_bfloat16* Qlp = g_qlo + ((size_t)bh*SEQ + q0) * HD;
    const __nv_bfloat16* Khp = g_khi + (size_t)bh*SEQ*HD;
    const __nv_bfloat16* Klp = g_klo + (size_t)bh*SEQ*HD;
    const __nv_bfloat16* Vhp = g_vthi + (size_t)bh*SEQ*HD;
    const __nv_bfloat16* Vlp = g_vtlo + (size_t)bh*SEQ*HD;

    int kt0, kt1;
    if (h == 0) { kt0 = 0; kt1 = SEQ / KT; }
    else {
        int lo = q0 - LOCALK; if (lo < 0) lo = 0;
        int hi = q0 + QT + LOCALK; if (hi > SEQ) hi = SEQ;
        kt0 = lo / KT; kt1 = hi / KT;
    }
    int nkt = kt1 - kt0;

    auto stage_kv = [&](int buf, int ktile) {
        uint32_t stg = sb + 2*AQB + buf*ASTG;
        int k0 = ktile * KT;
        #pragma unroll
        for (int j = 0; j < 4; j++) {
            int idx = tid + j*128;
            int r = idx >> 3, c = (idx & 7) * 8;
            uint32_t off = (uint32_t)(r*RSA + c) * 2;
            CP16(stg + 0*AQB + off, Khp + (size_t)(k0 + r)*HD + c);
            CP16(stg + 1*AQB + off, Klp + (size_t)(k0 + r)*HD + c);
            CP16(stg + 2*AQB + off, Vhp + (size_t)r*SEQ + k0 + c);
            CP16(stg + 3*AQB + off, Vlp + (size_t)r*SEQ + k0 + c);
        }
    };

    #pragma unroll
    for (int j = 0; j < 4; j++) {
        int idx = tid + j*128;
        int r = idx >> 3, c = (idx & 7) * 8;
        uint32_t off = (uint32_t)(r*RSA + c) * 2;
        CP16(sb + 0   + off, Qhp + (size_t)r*HD + c);
        CP16(sb + AQB + off, Qlp + (size_t)r*HD + c);
    }
    stage_kv(0, kt0);
    CP_COMMIT();

    uint32_t a_off = (uint32_t)((wid*16 + (lane & 15))*RSA + ((lane & 16) ? 8 : 0)) * 2;
    int b_row = (lane & 7) + ((lane & 16) ? 8 : 0);
    int b_half = (lane & 8) ? 8 : 0;
    int r0g = q0 + wid*16 + (lane >> 2);

    float o[8][4];
    #pragma unroll
    for (int nj = 0; nj < 8; nj++)
        #pragma unroll
        for (int r = 0; r < 4; r++) o[nj][r] = 0.f;
    float m0 = NEGF, m1 = NEGF, l0 = 0.f, l1 = 0.f;
    uint32_t qh[4][4], ql[4][4];

    for (int it = 0; it < nkt; it++) {
        uint32_t stg = sb + 2*AQB + (it & 1)*ASTG;
        if (it + 1 < nkt) { stage_kv((it+1) & 1, kt0 + it + 1); CP_COMMIT(); CP_WAIT1(); }
        else CP_WAIT0();
        __syncthreads();

        if (it == 0) {
            #pragma unroll
            for (int ks = 0; ks < 4; ks++) {
                ldsm4(sb + 0   + a_off + ks*32, qh[ks]);
                ldsm4(sb + AQB + a_off + ks*32, ql[ks]);
            }
        }

        float s[8][4];
        #pragma unroll
        for (int nj = 0; nj < 8; nj++)
            #pragma unroll
            for (int r = 0; r < 4; r++) s[nj][r] = 0.f;

        #pragma unroll
        for (int ks = 0; ks < 4; ks++) {
            uint32_t b[4][4];
            #pragma unroll
            for (int np = 0; np < 4; np++)
                ldsm4(stg + 0*AQB + ((b_row + np*16)*RSA + ks*16 + b_half)*2, b[np]);
            #pragma unroll
            for (int nj = 0; nj < 8; nj++) {
                uint32_t q0r = b[nj>>1][(nj&1)*2], q1r = b[nj>>1][(nj&1)*2+1];
                mma_bf16(s[nj], qh[ks][0], qh[ks][1], qh[ks][2], qh[ks][3], q0r, q1r);
                mma_bf16(s[nj], ql[ks][0], ql[ks][1], ql[ks][2], ql[ks][3], q0r, q1r);
            }
        }
        #pragma unroll
        for (int ks = 0; ks < 4; ks++) {
            uint32_t b[4][4];
            #pragma unroll
            for (int np = 0; np < 4; np++)
                ldsm4(stg + 1*AQB + ((b_row + np*16)*RSA + ks*16 + b_half)*2, b[np]);
            #pragma unroll
            for (int nj = 0; nj < 8; nj++)
                mma_bf16(s[nj], qh[ks][0], qh[ks][1], qh[ks][2], qh[ks][3],
                         b[nj>>1][(nj&1)*2], b[nj>>1][(nj&1)*2+1]);
        }

        int k0 = (kt0 + it) * KT;
        if (h != 0) {
            #pragma unroll
            for (int nj = 0; nj < 8; nj++) {
                int c0 = k0 + nj*8 + 2*(lane & 3);
                if (abs(r0g - c0)     > LOCALK) s[nj][0] = NEGF;
                if (abs(r0g - c0 - 1) > LOCALK) s[nj][1] = NEGF;
                if (abs(r0g + 8 - c0)     > LOCALK) s[nj][2] = NEGF;
                if (abs(r0g + 8 - c0 - 1) > LOCALK) s[nj][3] = NEGF;
            }
        }

        float mx0 = NEGF, mx1 = NEGF;
        #pragma unroll
        for (int nj = 0; nj < 8; nj++) {
            mx0 = fmaxf(mx0, fmaxf(s[nj][0], s[nj][1]));
            mx1 = fmaxf(mx1, fmaxf(s[nj][2], s[nj][3]));
        }
        mx0 = fmaxf(mx0, __shfl_xor_sync(0xffffffffu, mx0, 1));
        mx0 = fmaxf(mx0, __shfl_xor_sync(0xffffffffu, mx0, 2));
        mx1 = fmaxf(mx1, __shfl_xor_sync(0xffffffffu, mx1, 1));
        mx1 = fmaxf(mx1, __shfl_xor_sync(0xffffffffu, mx1, 2));
        float nm0 = fmaxf(m0, mx0), nm1 = fmaxf(m1, mx1);
        float cr0 = __expf(m0 - nm0), cr1 = __expf(m1 - nm1);
        m0 = nm0; m1 = nm1; l0 *= cr0; l1 *= cr1;
        #pragma unroll
        for (int nj = 0; nj < 8; nj++) {
            o[nj][0] *= cr0; o[nj][1] *= cr0;
            o[nj][2] *= cr1; o[nj][3] *= cr1;
        }
        float rs0 = 0.f, rs1 = 0.f;
        #pragma unroll
        for (int nj = 0; nj < 8; nj++) {
            float p0 = __expf(s[nj][0] - m0), p1 = __expf(s[nj][1] - m0);
            float p2 = __expf(s[nj][2] - m1), p3 = __expf(s[nj][3] - m1);
            rs0 += p0 + p1; rs1 += p2 + p3;
            uint32_t h01 = prmt_hi(p0, p1), h23 = prmt_hi(p2, p3);
            uint32_t lo01 = packbf(p0 - truncbf(p0), p1 - truncbf(p1));
            uint32_t lo23 = packbf(p2 - truncbf(p2), p3 - truncbf(p3));
            s[nj][0] = __uint_as_float(h01);  s[nj][1] = __uint_as_float(h23);
            s[nj][2] = __uint_as_float(lo01); s[nj][3] = __uint_as_float(lo23);
        }
        rs0 += __shfl_xor_sync(0xffffffffu, rs0, 1);
        rs0 += __shfl_xor_sync(0xffffffffu, rs0, 2);
        rs1 += __shfl_xor_sync(0xffffffffu, rs1, 1);
        rs1 += __shfl_xor_sync(0xffffffffu, rs1, 2);
        l0 += rs0; l1 += rs1;

        #pragma unroll
        for (int kc = 0; kc < 4; kc++) {
            uint32_t ah0 = __float_as_uint(s[2*kc][0]),   ah1 = __float_as_uint(s[2*kc][1]);
            uint32_t ah2 = __float_as_uint(s[2*kc+1][0]), ah3 = __float_as_uint(s[2*kc+1][1]);
            uint32_t al0 = __float_as_uint(s[2*kc][2]),   al1 = __float_as_uint(s[2*kc][3]);
            uint32_t al2 = __float_as_uint(s[2*kc+1][2]), al3 = __float_as_uint(s[2*kc+1][3]);
            uint32_t b[4][4];
            #pragma unroll
            for (int np = 0; np < 4; np++)
                ldsm4(stg + 2*AQB + ((b_row + np*16)*RSA + kc*16 + b_half)*2, b[np]);
            #pragma unroll
            for (int nj = 0; nj < 8; nj++) {
                uint32_t q0r = b[nj>>1][(nj&1)*2], q1r = b[nj>>1][(nj&1)*2+1];
                mma_bf16(o[nj], ah0, ah1, ah2, ah3, q0r, q1r);
                mma_bf16(o[nj], al0, al1, al2, al3, q0r, q1r);
            }
            #pragma unroll
            for (int np = 0; np < 4; np++)
                ldsm4(stg + 3*AQB + ((b_row + np*16)*RSA + kc*16 + b_half)*2, b[np]);
            #pragma unroll
            for (int nj = 0; nj < 8; nj++)
                mma_bf16(o[nj], ah0, ah1, ah2, ah3,
                         b[nj>>1][(nj&1)*2], b[nj>>1][(nj&1)*2+1]);
        }
        __syncthreads();
    }

    // Epilogue: normalize, fp16 split, store
    float inv0 = 1.f / l0, inv1 = 1.f / l1;
    #pragma unroll
    for (int nj = 0; nj < 8; nj++) {
        int d = nj*8 + 2*(lane & 3);
        float v0 = o[nj][0]*inv0, v1 = o[nj][1]*inv0;
        float v2 = o[nj][2]*inv1, v3 = o[nj][3]*inv1;
        __half h0 = __float2half_rn(v0), h1 = __float2half_rn(v1);
        __half h2 = __float2half_rn(v2), h3 = __float2half_rn(v3);
        __half r0 = __float2half_rn(v0 - __half2float(h0));
        __half r1 = __float2half_rn(v1 - __half2float(h1));
        __half r2 = __float2half_rn(v2 - __half2float(h2));
        __half r3 = __float2half_rn(v3 - __half2float(h3));
        size_t base0 = ((size_t)(bb*SEQ + r0g)) * EMB + h*HD + d;
        size_t base1 = ((size_t)(bb*SEQ + r0g + 8)) * EMB + h*HD + d;
        *(__half2*)(g_ahi + base0) = __halves2half2(h0, h1);
        *(__half2*)(g_alo + base0) = __halves2half2(r0, r1);
        *(__half2*)(g_ahi + base1) = __halves2half2(h2, h3);
        *(__half2*)(g_alo + base1) = __halves2half2(r2, r3);
    }
}

// ============================================================================
// Launch
// ============================================================================
extern "C" void kernel_launch(void* const* d_in, const int* in_sizes, int n_in,
                              void* d_out, int out_size)
{
    (void)in_sizes; (void)n_in; (void)out_size;
    const float* x  = (const float*)d_in[0];
    const float* wq = (const float*)d_in[1];
    const float* bq = (const float*)d_in[2];
    const float* wk = (const float*)d_in[3];
    const float* bk = (const float*)d_in[4];
    const float* wv = (const float*)d_in[5];
    const float* bv = (const float*)d_in[6];
    const float* wo = (const float*)d_in[7];
    const float* bo = (const float*)d_in[8];
    float* out = (float*)d_out;

    cudaFuncSetAttribute(gemm_hmma, cudaFuncAttributeMaxDynamicSharedMemorySize, GSMEM);
    cudaFuncSetAttribute(attn_tc,   cudaFuncAttributeMaxDynamicSharedMemorySize, ASMEM);

    split_kernel<<<SZ/4/256, 256>>>(x,  0, SZ/4);
    split_kernel<<<EMB*EMB/4/256, 256>>>(wq, 1, EMB*EMB/4);
    split_kernel<<<EMB*EMB/4/256, 256>>>(wk, 2, EMB*EMB/4);
    split_kernel<<<EMB*EMB/4/256, 256>>>(wv, 3, EMB*EMB/4);
    split_kernel<<<EMB*EMB/4/256, 256>>>(wo, 4, EMB*EMB/4);

    // Fused QKV: grid.x = 3 weights x 8 N-tiles
    gemm_hmma<<<dim3(24, 64), 256, GSMEM>>>(bq, bk, bv, nullptr, 0, 1);

    attn_tc<<<dim3(SEQ/QT, B_*NH), 128, ASMEM>>>();

    // O projection
    gemm_hmma<<<dim3(8, 64), 256, GSMEM>>>(bo, nullptr, nullptr, out, 1, 0);
}